// round 1
// baseline (speedup 1.0000x reference)
#include <cuda_runtime.h>

#define NN 32
#define CC 64
#define KK 3
#define TT 300
#define VV 25
#define HH 4
#define DD 16
#define CO 64
#define OC (KK*CO)   // 192
#define SFS 65       // padded row stride for [V][C] shared arrays

struct Smem {
    float fa[VV][SFS];     // BN1'd input, [v][c]
    float qn[VV][SFS];     // LayerNorm'd (reused later as xo)
    float q[VV][SFS];
    float k[VV][SFS];
    float v[VV][SFS];
    float attn[HH][VV][VV];
    float fc1[OC][VV];     // conv branch pre-A, [o][v]
    float A[KK*VV*VV];
    float w1s[CC], w1b[CC], w2s[CC], w2b[CC];
};

extern __shared__ float smem_raw[];

__global__ void __launch_bounds__(256) intent_gcn_fused(
    const float* __restrict__ x,   const float* __restrict__ Ag,
    const float* __restrict__ bn1_g, const float* __restrict__ bn1_b,
    const float* __restrict__ bn1_m, const float* __restrict__ bn1_v,
    const float* __restrict__ conv_w, const float* __restrict__ conv_b,
    const float* __restrict__ ln_g,  const float* __restrict__ ln_b,
    const float* __restrict__ wq, const float* __restrict__ wk,
    const float* __restrict__ wv, const float* __restrict__ fc_w,
    const float* __restrict__ gate_p,
    const float* __restrict__ bn2_g, const float* __restrict__ bn2_b,
    const float* __restrict__ bn2_m, const float* __restrict__ bn2_v,
    float* __restrict__ out)
{
    Smem* S = (Smem*)smem_raw;
    const int tid  = threadIdx.x;
    const int lane = tid & 31;
    const int wid  = tid >> 5;
    const int nt = blockIdx.x;
    const int n  = nt / TT;
    const int t  = nt - n * TT;

    // ---- stage BN params + A ----
    if (tid < CC) {
        float s1 = bn1_g[tid] * rsqrtf(bn1_v[tid] + 1e-5f);
        S->w1s[tid] = s1;
        S->w1b[tid] = bn1_b[tid] - bn1_m[tid] * s1;
        float s2 = bn2_g[tid] * rsqrtf(bn2_v[tid] + 1e-5f);
        S->w2s[tid] = s2;
        S->w2b[tid] = bn2_b[tid] - bn2_m[tid] * s2;
    }
    for (int i = tid; i < KK*VV*VV; i += 256) S->A[i] = Ag[i];
    __syncthreads();

    // ---- load x slice, apply BN1 -> s_fa[v][c] ----
    const float* xp = x + n * (CC*TT*VV) + t * VV;
    for (int i = tid; i < CC*VV; i += 256) {
        int c = i / VV;
        int v = i - c * VV;
        float val = xp[c * (TT*VV) + v];
        S->fa[v][c] = val * S->w1s[c] + S->w1b[c];
    }
    __syncthreads();

    // ---- LayerNorm per node row (warp per row) -> s_qn ----
    for (int v = wid; v < VV; v += 8) {
        float a0 = S->fa[v][lane];
        float a1 = S->fa[v][lane + 32];
        float s = a0 + a1;
        #pragma unroll
        for (int o = 16; o; o >>= 1) s += __shfl_xor_sync(0xffffffffu, s, o);
        float mu = s * (1.0f / 64.0f);
        float d0 = a0 - mu, d1 = a1 - mu;
        float ss = d0*d0 + d1*d1;
        #pragma unroll
        for (int o = 16; o; o >>= 1) ss += __shfl_xor_sync(0xffffffffu, ss, o);
        float rstd = rsqrtf(ss * (1.0f / 64.0f) + 1e-6f);
        S->qn[v][lane]      = d0 * rstd * ln_g[lane]      + ln_b[lane];
        S->qn[v][lane + 32] = d1 * rstd * ln_g[lane + 32] + ln_b[lane + 32];
    }
    __syncthreads();

    // ---- QKV projections: thread owns (v, 4 consecutive d) ----
    for (int item = tid; item < VV * 16; item += 256) {
        int v  = item >> 4;
        int d4 = (item & 15) << 2;
        float aq0=0,aq1=0,aq2=0,aq3=0;
        float ak0=0,ak1=0,ak2=0,ak3=0;
        float av0=0,av1=0,av2=0,av3=0;
        #pragma unroll 8
        for (int c = 0; c < CC; ++c) {
            float fq = S->qn[v][c];
            float fk = S->fa[v][c];
            float4 q4 = *(const float4*)(wq + c*CC + d4);
            float4 k4 = *(const float4*)(wk + c*CC + d4);
            float4 v4 = *(const float4*)(wv + c*CC + d4);
            aq0 += fq*q4.x; aq1 += fq*q4.y; aq2 += fq*q4.z; aq3 += fq*q4.w;
            ak0 += fk*k4.x; ak1 += fk*k4.y; ak2 += fk*k4.z; ak3 += fk*k4.w;
            av0 += fk*v4.x; av1 += fk*v4.y; av2 += fk*v4.z; av3 += fk*v4.w;
        }
        S->q[v][d4+0]=aq0; S->q[v][d4+1]=aq1; S->q[v][d4+2]=aq2; S->q[v][d4+3]=aq3;
        S->k[v][d4+0]=ak0; S->k[v][d4+1]=ak1; S->k[v][d4+2]=ak2; S->k[v][d4+3]=ak3;
        S->v[v][d4+0]=av0; S->v[v][d4+1]=av1; S->v[v][d4+2]=av2; S->v[v][d4+3]=av3;
    }

    // ---- conv branch stage 1: fc1[o][v] = conv_b[o] + sum_c fa[v][c]*W[o][c] ----
    for (int item = tid; item < OC * VV; item += 256) {
        int o = item / VV;
        int v = item - o * VV;
        float acc = conv_b[o];
        #pragma unroll 8
        for (int c = 0; c < CC; c += 4) {
            float4 w4 = *(const float4*)(conv_w + o*CC + c);
            acc += S->fa[v][c+0]*w4.x + S->fa[v][c+1]*w4.y
                 + S->fa[v][c+2]*w4.z + S->fa[v][c+3]*w4.w;
        }
        S->fc1[o][v] = acc;
    }
    __syncthreads();

    // ---- attention scores + softmax: warp per (h, query-row) ----
    for (int r = wid; r < HH * VV; r += 8) {
        int h  = r / VV;
        int vq = r - h * VV;
        int off = h * DD;
        float sc = -1e30f;
        if (lane < VV) {
            float acc = 0.0f;
            #pragma unroll
            for (int d = 0; d < DD; ++d)
                acc += S->q[vq][off + d] * S->k[lane][off + d];
            sc = acc * 0.25f;   // 1/sqrt(DK), DK=16
        }
        float m = sc;
        #pragma unroll
        for (int o = 16; o; o >>= 1) m = fmaxf(m, __shfl_xor_sync(0xffffffffu, m, o));
        float e = (lane < VV) ? __expf(sc - m) : 0.0f;
        float s = e;
        #pragma unroll
        for (int o = 16; o; o >>= 1) s += __shfl_xor_sync(0xffffffffu, s, o);
        if (lane < VV) S->attn[h][vq][lane] = e / s;
    }
    __syncthreads();

    // ---- xo = attn @ V  (reuse s_qn as xo) ----
    for (int i = tid; i < VV * CC; i += 256) {
        int v = i >> 6;
        int e = i & 63;
        int h = e >> 4;
        float acc = 0.0f;
        #pragma unroll
        for (int w = 0; w < VV; ++w)
            acc += S->attn[h][v][w] * S->v[w][e];
        S->qn[v][e] = acc;
    }
    __syncthreads();

    // ---- final: fc epilogue + residual, graph contraction, merge, BN2, ReLU ----
    const float gate = *gate_p;
    float* op = out + n * (CC*TT*VV) + t * VV;
    for (int i = tid; i < CC * VV; i += 256) {
        int c = i / VV;
        int w = i - c * VV;
        // adaptive branch: f_a[w][c] = xo[w]·fc_w[:,c] + fa[w][c]
        float fa_acc = S->fa[w][c];
        #pragma unroll 8
        for (int e = 0; e < CC; ++e)
            fa_acc += S->qn[w][e] * fc_w[e*CC + c];
        // fixed branch: sum_k sum_v fc1[k*64+c][v] * A[k][v][w]
        float fc_acc = 0.0f;
        #pragma unroll
        for (int k = 0; k < KK; ++k) {
            const float* Ak = &S->A[k*VV*VV];
            const float* f1 = S->fc1[k*CO + c];
            #pragma unroll 5
            for (int v = 0; v < VV; ++v)
                fc_acc += f1[v] * Ak[v*VV + w];
        }
        float f = (fa_acc * gate + fc_acc) * 0.5f;
        float r = f * S->w2s[c] + S->w2b[c];
        op[c * (TT*VV) + w] = fmaxf(r, 0.0f);
    }
}

extern "C" void kernel_launch(void* const* d_in, const int* in_sizes, int n_in,
                              void* d_out, int out_size)
{
    const float* x      = (const float*)d_in[0];
    const float* A      = (const float*)d_in[1];
    const float* bn1_g  = (const float*)d_in[2];
    const float* bn1_b  = (const float*)d_in[3];
    const float* bn1_m  = (const float*)d_in[4];
    const float* bn1_v  = (const float*)d_in[5];
    const float* conv_w = (const float*)d_in[6];
    const float* conv_b = (const float*)d_in[7];
    const float* ln_g   = (const float*)d_in[8];
    const float* ln_b   = (const float*)d_in[9];
    const float* wq     = (const float*)d_in[10];
    const float* wk     = (const float*)d_in[11];
    const float* wv     = (const float*)d_in[12];
    const float* fc_w   = (const float*)d_in[13];
    const float* gate   = (const float*)d_in[14];
    const float* bn2_g  = (const float*)d_in[15];
    const float* bn2_b  = (const float*)d_in[16];
    const float* bn2_m  = (const float*)d_in[17];
    const float* bn2_v  = (const float*)d_in[18];
    float* out = (float*)d_out;

    const int smem_bytes = (int)sizeof(Smem);
    cudaFuncSetAttribute(intent_gcn_fused,
                         cudaFuncAttributeMaxDynamicSharedMemorySize, smem_bytes);

    dim3 grid(NN * TT);
    intent_gcn_fused<<<grid, 256, smem_bytes>>>(
        x, A, bn1_g, bn1_b, bn1_m, bn1_v, conv_w, conv_b, ln_g, ln_b,
        wq, wk, wv, fc_w, gate, bn2_g, bn2_b, bn2_m, bn2_v, out);
}

// round 3
// speedup vs baseline: 1.6146x; 1.6146x over previous
#include <cuda_runtime.h>

#define NN 32
#define CC 64
#define KK 3
#define TT 300
#define VV 25
#define HH 4
#define DD 16
#define CO 64
#define OC (KK*CO)   // 192

typedef unsigned long long u64;

__device__ __forceinline__ u64 pk(float x) {
    u64 r; asm("mov.b64 %0, {%1, %1};" : "=l"(r) : "f"(x)); return r;
}
__device__ __forceinline__ u64 pk2(float x, float y) {
    u64 r; asm("mov.b64 %0, {%1, %2};" : "=l"(r) : "f"(x), "f"(y)); return r;
}
__device__ __forceinline__ void fma2(u64& d, u64 a, u64 b) {
    asm("fma.rn.f32x2 %0, %1, %2, %0;" : "+l"(d) : "l"(a), "l"(b));
}
__device__ __forceinline__ float2 up(u64 v) {
    float2 f; asm("mov.b64 {%0, %1}, %2;" : "=f"(f.x), "=f"(f.y) : "l"(v)); return f;
}

struct Smem {
    float w1s[CC], w1b[CC], w2s[CC], w2b[CC], lng[CC], lnb[CC]; // 384 floats
    float Apad[KK][VV][28];      // 2100
    float fa_vc[VV][68];         // 1700  BN1'd input, v-major
    float fa_cv[CC][28];         // 1792  BN1'd input, c-major
    float qn[VV][68];            // 1700  LayerNorm output
    float attn[HH][VV][28];      // 2800
    float xo[28][68];            // 1904  (28 rows: rows 25-27 zeroed, keeps tile reads defined)
    union {
        struct { float q[VV][68]; float kT[CC][28]; float vs[VV][68]; } a;
        float fc1[OC][28];
    } u;
};

extern __shared__ float smem_raw[];

__global__ void __launch_bounds__(256, 3) intent_gcn_fused(
    const float* __restrict__ x,   const float* __restrict__ Ag,
    const float* __restrict__ bn1_g, const float* __restrict__ bn1_b,
    const float* __restrict__ bn1_m, const float* __restrict__ bn1_v,
    const float* __restrict__ conv_w, const float* __restrict__ conv_b,
    const float* __restrict__ ln_g,  const float* __restrict__ ln_b,
    const float* __restrict__ wq, const float* __restrict__ wk,
    const float* __restrict__ wv, const float* __restrict__ fc_w,
    const float* __restrict__ gate_p,
    const float* __restrict__ bn2_g, const float* __restrict__ bn2_b,
    const float* __restrict__ bn2_m, const float* __restrict__ bn2_v,
    float* __restrict__ out)
{
    Smem* S = (Smem*)smem_raw;
    const int tid  = threadIdx.x;
    const int lane = tid & 31;
    const int wid  = tid >> 5;
    const int nt = blockIdx.x;
    const int n  = nt / TT;
    const int t  = nt - n * TT;

    // ---- stage BN/LN params + A (padded) ----
    if (tid < CC) {
        float s1 = bn1_g[tid] * rsqrtf(bn1_v[tid] + 1e-5f);
        S->w1s[tid] = s1;
        S->w1b[tid] = bn1_b[tid] - bn1_m[tid] * s1;
        float s2 = bn2_g[tid] * rsqrtf(bn2_v[tid] + 1e-5f);
        S->w2s[tid] = s2;
        S->w2b[tid] = bn2_b[tid] - bn2_m[tid] * s2;
        S->lng[tid] = ln_g[tid];
        S->lnb[tid] = ln_b[tid];
    }
    for (int i = tid; i < KK*VV*VV; i += 256) {
        int k = i / (VV*VV);
        int r = i - k * (VV*VV);
        int v = r / VV;
        int w = r - v * VV;
        S->Apad[k][v][w] = Ag[i];
    }
    // zero the xo pad rows (25..27) once; they are never written again
    if (tid < 3 * 68) {
        int r = tid / 68;
        int c = tid - r * 68;
        S->xo[VV + r][c] = 0.0f;
    }
    __syncthreads();

    // ---- load x slice, BN1 -> both layouts ----
    const float* xp = x + n * (CC*TT*VV) + t * VV;
    for (int i = tid; i < CC*VV; i += 256) {
        int c = i / VV;
        int v = i - c * VV;
        float val = xp[c * (TT*VV) + v] * S->w1s[c] + S->w1b[c];
        S->fa_vc[v][c] = val;
        S->fa_cv[c][v] = val;
    }
    __syncthreads();

    // ---- LayerNorm per node (warp per row) ----
    for (int v = wid; v < VV; v += 8) {
        float a0 = S->fa_vc[v][lane];
        float a1 = S->fa_vc[v][lane + 32];
        float s = a0 + a1;
        #pragma unroll
        for (int o = 16; o; o >>= 1) s += __shfl_xor_sync(0xffffffffu, s, o);
        float mu = s * (1.0f / 64.0f);
        float d0 = a0 - mu, d1 = a1 - mu;
        float ss = d0*d0 + d1*d1;
        #pragma unroll
        for (int o = 16; o; o >>= 1) ss += __shfl_xor_sync(0xffffffffu, ss, o);
        float rstd = rsqrtf(ss * (1.0f / 64.0f) + 1e-6f);
        S->qn[v][lane]      = d0 * rstd * S->lng[lane]      + S->lnb[lane];
        S->qn[v][lane + 32] = d1 * rstd * S->lng[lane + 32] + S->lnb[lane + 32];
    }
    __syncthreads();

    // ---- QKV projections: item = (vpair, 4d), FFMA2 ----
    // 208 items = 13 vpairs * 16 dgroups; lanes sharing a vpair -> LDS broadcast
    if (tid < 13 * 16) {
        int vp = tid >> 4;
        int dg = tid & 15;
        int v0 = vp * 2;
        int v1 = (v0 + 1 < VV) ? v0 + 1 : v0;
        bool two = (v0 + 1 < VV);
        int d4 = dg * 4;
        u64 aq0=0,aq1=0,aq2=0,aq3=0, ak0=0,ak1=0,ak2=0,ak3=0, av0=0,av1=0,av2=0,av3=0;
        #pragma unroll 4
        for (int c = 0; c < CC; ++c) {
            u64 pq0 = pk(S->qn[v0][c]);
            u64 pq1 = pk(S->qn[v1][c]);
            u64 pf0 = pk(S->fa_vc[v0][c]);
            u64 pf1 = pk(S->fa_vc[v1][c]);
            ulonglong2 wq2 = *(const ulonglong2*)(wq + c*CC + d4);
            ulonglong2 wk2 = *(const ulonglong2*)(wk + c*CC + d4);
            ulonglong2 wv2 = *(const ulonglong2*)(wv + c*CC + d4);
            fma2(aq0, pq0, wq2.x); fma2(aq1, pq0, wq2.y);
            fma2(aq2, pq1, wq2.x); fma2(aq3, pq1, wq2.y);
            fma2(ak0, pf0, wk2.x); fma2(ak1, pf0, wk2.y);
            fma2(ak2, pf1, wk2.x); fma2(ak3, pf1, wk2.y);
            fma2(av0, pf0, wv2.x); fma2(av1, pf0, wv2.y);
            fma2(av2, pf1, wv2.x); fma2(av3, pf1, wv2.y);
        }
        float2 a, b;
        a = up(aq0); b = up(aq1);
        *(float4*)&S->u.a.q[v0][d4] = make_float4(a.x, a.y, b.x, b.y);
        a = up(av0); b = up(av1);
        *(float4*)&S->u.a.vs[v0][d4] = make_float4(a.x, a.y, b.x, b.y);
        a = up(ak0); b = up(ak1);
        S->u.a.kT[d4+0][v0] = a.x; S->u.a.kT[d4+1][v0] = a.y;
        S->u.a.kT[d4+2][v0] = b.x; S->u.a.kT[d4+3][v0] = b.y;
        if (two) {
            a = up(aq2); b = up(aq3);
            *(float4*)&S->u.a.q[v1][d4] = make_float4(a.x, a.y, b.x, b.y);
            a = up(av2); b = up(av3);
            *(float4*)&S->u.a.vs[v1][d4] = make_float4(a.x, a.y, b.x, b.y);
            a = up(ak2); b = up(ak3);
            S->u.a.kT[d4+0][v1] = a.x; S->u.a.kT[d4+1][v1] = a.y;
            S->u.a.kT[d4+2][v1] = b.x; S->u.a.kT[d4+3][v1] = b.y;
        }
    }
    __syncthreads();

    // ---- attention scores + softmax (warp per (h, query row)) ----
    for (int r = wid; r < HH * VV; r += 8) {
        int h  = r / VV;
        int vq = r - h * VV;
        int off = h * DD;
        float sc = -1e30f;
        if (lane < VV) {
            float acc = 0.0f;
            #pragma unroll
            for (int d = 0; d < DD; ++d)
                acc += S->u.a.q[vq][off + d] * S->u.a.kT[off + d][lane];
            sc = acc * 0.25f;
        }
        float m = sc;
        #pragma unroll
        for (int o = 16; o; o >>= 1) m = fmaxf(m, __shfl_xor_sync(0xffffffffu, m, o));
        float e = (lane < VV) ? __expf(sc - m) : 0.0f;
        float s = e;
        #pragma unroll
        for (int o = 16; o; o >>= 1) s += __shfl_xor_sync(0xffffffffu, s, o);
        if (lane < VV) S->attn[h][vq][lane] = e / s;
    }
    __syncthreads();

    // ---- xo = attn @ V : item = (v, 8 e's) ----
    if (tid < VV * 8) {
        int v  = tid >> 3;
        int e8 = (tid & 7) * 8;
        int h  = e8 >> 4;
        u64 a0=0, a1=0, a2=0, a3=0;
        #pragma unroll 5
        for (int w = 0; w < VV; ++w) {
            u64 ap = pk(S->attn[h][v][w]);
            ulonglong2 p0 = *(const ulonglong2*)&S->u.a.vs[w][e8];
            ulonglong2 p1 = *(const ulonglong2*)&S->u.a.vs[w][e8 + 4];
            fma2(a0, ap, p0.x); fma2(a1, ap, p0.y);
            fma2(a2, ap, p1.x); fma2(a3, ap, p1.y);
        }
        float2 f;
        f = up(a0); S->xo[v][e8+0] = f.x; S->xo[v][e8+1] = f.y;
        f = up(a1); S->xo[v][e8+2] = f.x; S->xo[v][e8+3] = f.y;
        f = up(a2); S->xo[v][e8+4] = f.x; S->xo[v][e8+5] = f.y;
        f = up(a3); S->xo[v][e8+6] = f.x; S->xo[v][e8+7] = f.y;
    }
    __syncthreads();  // xo done; q/kT/vs now dead -> union reused as fc1

    // ---- conv branch: fc1[o][v] tile (2 o's x 4 v's), FFMA2 ----
    for (int it = tid; it < 96 * 7; it += 256) {
        int og = it / 7;
        int vg = it - og * 7;
        int o0 = og * 2;
        int v4 = vg * 4;
        u64 acc00 = pk(conv_b[o0]);     u64 acc01 = acc00;
        u64 acc10 = pk(conv_b[o0 + 1]); u64 acc11 = acc10;
        #pragma unroll 2
        for (int c = 0; c < CC; c += 4) {
            ulonglong2 f0 = *(const ulonglong2*)&S->fa_cv[c+0][v4];
            ulonglong2 f1 = *(const ulonglong2*)&S->fa_cv[c+1][v4];
            ulonglong2 f2 = *(const ulonglong2*)&S->fa_cv[c+2][v4];
            ulonglong2 f3 = *(const ulonglong2*)&S->fa_cv[c+3][v4];
            float4 w0 = *(const float4*)(conv_w + o0*CC + c);
            float4 w1 = *(const float4*)(conv_w + (o0+1)*CC + c);
            fma2(acc00, f0.x, pk(w0.x)); fma2(acc01, f0.y, pk(w0.x));
            fma2(acc00, f1.x, pk(w0.y)); fma2(acc01, f1.y, pk(w0.y));
            fma2(acc00, f2.x, pk(w0.z)); fma2(acc01, f2.y, pk(w0.z));
            fma2(acc00, f3.x, pk(w0.w)); fma2(acc01, f3.y, pk(w0.w));
            fma2(acc10, f0.x, pk(w1.x)); fma2(acc11, f0.y, pk(w1.x));
            fma2(acc10, f1.x, pk(w1.y)); fma2(acc11, f1.y, pk(w1.y));
            fma2(acc10, f2.x, pk(w1.z)); fma2(acc11, f2.y, pk(w1.z));
            fma2(acc10, f3.x, pk(w1.w)); fma2(acc11, f3.y, pk(w1.w));
        }
        float2 a, b;
        a = up(acc00); b = up(acc01);
        *(float4*)&S->u.fc1[o0][v4] = make_float4(a.x, a.y, b.x, b.y);
        a = up(acc10); b = up(acc11);
        *(float4*)&S->u.fc1[o0+1][v4] = make_float4(a.x, a.y, b.x, b.y);
    }
    __syncthreads();

    // ---- final: tile (2 c's x 4 w's): fc epilogue + residual + graph + BN2 + ReLU ----
    if (tid < 32 * 7) {
        int cg = tid / 7;
        int wg = tid - cg * 7;
        int c0 = cg * 2;
        int w4 = wg * 4;
        const float gate = __ldg(gate_p);
        // adaptive branch: sum_e xo[w][e] * fc_w[e][c]
        u64 aA00=0, aA01=0, aA10=0, aA11=0;
        #pragma unroll 4
        for (int e = 0; e < CC; ++e) {
            u64 xp0 = pk2(S->xo[w4+0][e], S->xo[w4+1][e]);
            u64 xp1 = pk2(S->xo[w4+2][e], S->xo[w4+3][e]);
            float2 fw = *(const float2*)(fc_w + e*CC + c0);
            u64 b0 = pk(fw.x), b1 = pk(fw.y);
            fma2(aA00, xp0, b0); fma2(aA01, xp1, b0);
            fma2(aA10, xp0, b1); fma2(aA11, xp1, b1);
        }
        // fixed branch: sum_k sum_v fc1[k*64+c][v] * A[k][v][w]
        u64 aG00=0, aG01=0, aG10=0, aG11=0;
        #pragma unroll
        for (int k = 0; k < KK; ++k) {
            const float* f1a = S->u.fc1[k*CO + c0];
            const float* f1b = S->u.fc1[k*CO + c0 + 1];
            #pragma unroll 5
            for (int v = 0; v < VV; ++v) {
                u64 b0 = pk(f1a[v]);
                u64 b1 = pk(f1b[v]);
                ulonglong2 a2 = *(const ulonglong2*)&S->Apad[k][v][w4];
                fma2(aG00, b0, a2.x); fma2(aG01, b0, a2.y);
                fma2(aG10, b1, a2.x); fma2(aG11, b1, a2.y);
            }
        }
        float* op = out + n * (CC*TT*VV) + t * VV;
        float fcv[2][4], gcv[2][4];
        float2 f;
        f = up(aA00); fcv[0][0]=f.x; fcv[0][1]=f.y;
        f = up(aA01); fcv[0][2]=f.x; fcv[0][3]=f.y;
        f = up(aA10); fcv[1][0]=f.x; fcv[1][1]=f.y;
        f = up(aA11); fcv[1][2]=f.x; fcv[1][3]=f.y;
        f = up(aG00); gcv[0][0]=f.x; gcv[0][1]=f.y;
        f = up(aG01); gcv[0][2]=f.x; gcv[0][3]=f.y;
        f = up(aG10); gcv[1][0]=f.x; gcv[1][1]=f.y;
        f = up(aG11); gcv[1][2]=f.x; gcv[1][3]=f.y;
        #pragma unroll
        for (int cj = 0; cj < 2; ++cj) {
            int c = c0 + cj;
            float s2 = S->w2s[c], b2 = S->w2b[c];
            #pragma unroll
            for (int wj = 0; wj < 4; ++wj) {
                int w = w4 + wj;
                if (w < VV) {
                    float fa_tot = fcv[cj][wj] + S->fa_cv[c][w];
                    float fv = (fa_tot * gate + gcv[cj][wj]) * 0.5f;
                    float r = fv * s2 + b2;
                    op[c * (TT*VV) + w] = fmaxf(r, 0.0f);
                }
            }
        }
    }
}

extern "C" void kernel_launch(void* const* d_in, const int* in_sizes, int n_in,
                              void* d_out, int out_size)
{
    const float* x      = (const float*)d_in[0];
    const float* A      = (const float*)d_in[1];
    const float* bn1_g  = (const float*)d_in[2];
    const float* bn1_b  = (const float*)d_in[3];
    const float* bn1_m  = (const float*)d_in[4];
    const float* bn1_v  = (const float*)d_in[5];
    const float* conv_w = (const float*)d_in[6];
    const float* conv_b = (const float*)d_in[7];
    const float* ln_g   = (const float*)d_in[8];
    const float* ln_b   = (const float*)d_in[9];
    const float* wq     = (const float*)d_in[10];
    const float* wk     = (const float*)d_in[11];
    const float* wv     = (const float*)d_in[12];
    const float* fc_w   = (const float*)d_in[13];
    const float* gate   = (const float*)d_in[14];
    const float* bn2_g  = (const float*)d_in[15];
    const float* bn2_b  = (const float*)d_in[16];
    const float* bn2_m  = (const float*)d_in[17];
    const float* bn2_v  = (const float*)d_in[18];
    float* out = (float*)d_out;

    const int smem_bytes = (int)sizeof(Smem);
    cudaFuncSetAttribute(intent_gcn_fused,
                         cudaFuncAttributeMaxDynamicSharedMemorySize, smem_bytes);

    dim3 grid(NN * TT);
    intent_gcn_fused<<<grid, 256, smem_bytes>>>(
        x, A, bn1_g, bn1_b, bn1_m, bn1_v, conv_w, conv_b, ln_g, ln_b,
        wq, wk, wv, fc_w, gate, bn2_g, bn2_b, bn2_m, bn2_v, out);
}